// round 2
// baseline (speedup 1.0000x reference)
#include <cuda_runtime.h>

#define NN 50000
#define NE 800000
#define FEAT 128
#define HID 64
#define NCLS 12
#define SCAN_CHUNK 1024
#define NB ((NN + SCAN_CHUNK - 1) / SCAN_CHUNK)   // 49

// ---------------- scratch (static device globals; no allocation) -------------
__device__ __align__(16) int   g_deg[NN];
__device__ __align__(16) int   g_rowptr[NN + 1];
__device__ __align__(16) int   g_cursor[NN];
__device__ __align__(16) int   g_partial[NB + 8];
__device__ __align__(16) int   g_csr[NE];
__device__ __align__(16) float g_dinv[NN];
__device__ __align__(16) float g_xws[NN * HID];   // (A @ W) * dinv, per layer
__device__ __align__(16) float g_h1[NN * HID];    // layer-1 activations

// ---------------- CSR build --------------------------------------------------
__global__ void k_zero_deg() {
    int i = blockIdx.x * blockDim.x + threadIdx.x;
    if (i < NN) g_deg[i] = 0;
}

__global__ void k_count(const int* __restrict__ dst) {
    int e = blockIdx.x * blockDim.x + threadIdx.x;
    if (e < NE) atomicAdd(&g_deg[dst[e]], 1);
}

// per-chunk (1024) sums
__global__ void k_scan1() {
    __shared__ int wsum[8];
    int t = threadIdx.x, b = blockIdx.x;
    int base = b * SCAN_CHUNK + t * 4;
    int s = 0;
#pragma unroll
    for (int i = 0; i < 4; i++)
        if (base + i < NN) s += g_deg[base + i];
#pragma unroll
    for (int d = 16; d; d >>= 1) s += __shfl_xor_sync(0xffffffffu, s, d);
    if ((t & 31) == 0) wsum[t >> 5] = s;
    __syncthreads();
    if (t == 0) {
        int tot = 0;
#pragma unroll
        for (int i = 0; i < 8; i++) tot += wsum[i];
        g_partial[b] = tot;
    }
}

// exclusive scan of the NB partials (NB=49 <= 64 lanes over 2 warps)
__global__ void k_scan2() {
    __shared__ int w0sum;
    int t = threadIdx.x;               // 64 threads
    int lane = t & 31, wid = t >> 5;
    int v = (t < NB) ? g_partial[t] : 0;
    int sc = v;
#pragma unroll
    for (int d = 1; d < 32; d <<= 1) {
        int n = __shfl_up_sync(0xffffffffu, sc, d);
        if (lane >= d) sc += n;
    }
    if (wid == 0 && lane == 31) w0sum = sc;
    __syncthreads();
    if (wid == 1) sc += w0sum;
    if (t < NB) g_partial[t] = sc - v;  // exclusive
}

// final: rowptr (exclusive), cursor copy, dinv = rsqrt(deg+1)
__global__ void k_scan3() {
    __shared__ int warp_sums[8];
    int t = threadIdx.x, b = blockIdx.x;
    int lane = t & 31, wid = t >> 5;
    int base = b * SCAN_CHUNK + t * 4;
    int v[4];
#pragma unroll
    for (int i = 0; i < 4; i++) v[i] = (base + i < NN) ? g_deg[base + i] : 0;
    int s = v[0] + v[1] + v[2] + v[3];
    int sc = s;
#pragma unroll
    for (int d = 1; d < 32; d <<= 1) {
        int n = __shfl_up_sync(0xffffffffu, sc, d);
        if (lane >= d) sc += n;
    }
    if (lane == 31) warp_sums[wid] = sc;
    __syncthreads();
    if (wid == 0) {
        int ws = (lane < 8) ? warp_sums[lane] : 0;
#pragma unroll
        for (int d = 1; d < 8; d <<= 1) {
            int n = __shfl_up_sync(0xffffffffu, ws, d);
            if (lane >= d) ws += n;
        }
        if (lane < 8) warp_sums[lane] = ws;  // inclusive per-warp totals
    }
    __syncthreads();
    int run = g_partial[b] + (wid ? warp_sums[wid - 1] : 0) + (sc - s);
#pragma unroll
    for (int i = 0; i < 4; i++) {
        int idx = base + i;
        if (idx < NN) {
            g_rowptr[idx] = run;
            g_cursor[idx] = run;
            g_dinv[idx]   = rsqrtf((float)v[i] + 1.0f);
            run += v[i];
        }
    }
    if (b == 0 && t == 0) g_rowptr[NN] = NE;
}

__global__ void k_fill(const int* __restrict__ src,
                       const int* __restrict__ dst) {
    int e = blockIdx.x * blockDim.x + threadIdx.x;
    if (e < NE) {
        int d = dst[e];
        int pos = atomicAdd(&g_cursor[d], 1);
        g_csr[pos] = src[e];
    }
}

// ---------------- GEMM: C = (A @ W) * dinv[row],  C -> g_xws ----------------
// A: [NN, K] (external x, or g_h1), W: [K, 64]. Tile: 64 rows/block, 256 thr,
// each thread computes a 4x4 micro-tile.
template <int K, bool A_FROM_H1>
__global__ void k_gemm(const float* __restrict__ Aext, const float* __restrict__ W) {
    const int KB = 64;
    __shared__ float As[64][KB + 4];
    __shared__ float Ws[KB][HID];
    const float* A = A_FROM_H1 ? (const float*)g_h1 : Aext;
    int tid = threadIdx.x;
    int tx = tid & 15;      // 4 output cols: tx*4..+3
    int ty = tid >> 4;      // 4 output rows: ty*4..+3
    int row0 = blockIdx.x * 64;
    float acc[4][4] = {};
    for (int kb = 0; kb < K; kb += KB) {
        // load A tile (64 x KB)
        for (int i = tid; i < 64 * (KB / 4); i += 256) {
            int r  = i >> 4;
            int c4 = i & 15;
            float4 v = make_float4(0.f, 0.f, 0.f, 0.f);
            int gr = row0 + r;
            if (gr < NN) v = *(const float4*)&A[gr * K + kb + c4 * 4];
            *(float4*)&As[r][c4 * 4] = v;
        }
        // load W tile (KB x 64)
        for (int i = tid; i < KB * (HID / 4); i += 256) {
            int r  = i >> 4;
            int c4 = i & 15;
            *(float4*)&Ws[r][c4 * 4] = *(const float4*)&W[(kb + r) * HID + c4 * 4];
        }
        __syncthreads();
#pragma unroll 8
        for (int k = 0; k < KB; k++) {
            float a0 = As[ty * 4 + 0][k];
            float a1 = As[ty * 4 + 1][k];
            float a2 = As[ty * 4 + 2][k];
            float a3 = As[ty * 4 + 3][k];
            float4 w = *(const float4*)&Ws[k][tx * 4];
            acc[0][0] += a0 * w.x; acc[0][1] += a0 * w.y; acc[0][2] += a0 * w.z; acc[0][3] += a0 * w.w;
            acc[1][0] += a1 * w.x; acc[1][1] += a1 * w.y; acc[1][2] += a1 * w.z; acc[1][3] += a1 * w.w;
            acc[2][0] += a2 * w.x; acc[2][1] += a2 * w.y; acc[2][2] += a2 * w.z; acc[2][3] += a2 * w.w;
            acc[3][0] += a3 * w.x; acc[3][1] += a3 * w.y; acc[3][2] += a3 * w.z; acc[3][3] += a3 * w.w;
        }
        __syncthreads();
    }
#pragma unroll
    for (int i = 0; i < 4; i++) {
        int r = row0 + ty * 4 + i;
        if (r < NN) {
            float sc = g_dinv[r];
            float4 o = make_float4(acc[i][0] * sc, acc[i][1] * sc,
                                   acc[i][2] * sc, acc[i][3] * sc);
            *(float4*)&g_xws[r * HID + tx * 4] = o;
        }
    }
}

// ---------------- aggregation: warp per dst node ----------------------------
// acc = sum_{j in N(i)} xws[j] ; out = dinv[i]*(acc + xws[i]) + b
__device__ __forceinline__ void agg_row(int node, int lane, float& a0, float& a1) {
    int beg = g_rowptr[node];
    int end = g_rowptr[node + 1];
    a0 = 0.f; a1 = 0.f;
    for (int base = beg; base < end; base += 32) {
        int idx = base + lane;
        int s_l = (idx < end) ? g_csr[idx] : 0;
        int iters = end - base;
        if (iters > 32) iters = 32;
#pragma unroll 4
        for (int j = 0; j < iters; j++) {
            int s = __shfl_sync(0xffffffffu, s_l, j);
            float2 v = *(const float2*)&g_xws[s * HID + 2 * lane];
            a0 += v.x;
            a1 += v.y;
        }
    }
}

__global__ void k_agg1(const float* __restrict__ b1) {
    int warp = (blockIdx.x * blockDim.x + threadIdx.x) >> 5;
    int lane = threadIdx.x & 31;
    if (warp >= NN) return;
    float a0, a1;
    agg_row(warp, lane, a0, a1);
    float dd = g_dinv[warp];
    float2 sv = *(const float2*)&g_xws[warp * HID + 2 * lane];
    float r0 = fmaxf(fmaf(dd, a0 + sv.x, b1[2 * lane + 0]), 0.f);
    float r1 = fmaxf(fmaf(dd, a1 + sv.y, b1[2 * lane + 1]), 0.f);
    *(float2*)&g_h1[warp * HID + 2 * lane] = make_float2(r0, r1);
}

// layer-2 aggregation fused with the 64->12 FC + bfc. Writes d_out directly.
__global__ void k_agg2(const float* __restrict__ b2, const float* __restrict__ Wfc,
                       const float* __restrict__ bfc, float* __restrict__ out) {
    __shared__ float sW[HID * NCLS];
    __shared__ float sb2[HID];
    __shared__ float sbfc[NCLS];
    int tid = threadIdx.x;
    for (int i = tid; i < HID * NCLS; i += 256) sW[i] = Wfc[i];
    if (tid < HID)  sb2[tid]  = b2[tid];
    if (tid < NCLS) sbfc[tid] = bfc[tid];
    __syncthreads();

    int warp = (blockIdx.x * blockDim.x + tid) >> 5;
    int lane = tid & 31;
    if (warp >= NN) return;
    float a0, a1;
    agg_row(warp, lane, a0, a1);
    float dd = g_dinv[warp];
    float2 sv = *(const float2*)&g_xws[warp * HID + 2 * lane];
    float t0 = fmaxf(fmaf(dd, a0 + sv.x, sb2[2 * lane + 0]), 0.f);
    float t1 = fmaxf(fmaf(dd, a1 + sv.y, sb2[2 * lane + 1]), 0.f);

    // FC: out[c] = sum_k h2[k] * Wfc[k][c] + bfc[c]
    float res = 0.f;
#pragma unroll
    for (int c = 0; c < NCLS; c++) {
        float p = t0 * sW[(2 * lane + 0) * NCLS + c] + t1 * sW[(2 * lane + 1) * NCLS + c];
        p += __shfl_xor_sync(0xffffffffu, p, 16);
        p += __shfl_xor_sync(0xffffffffu, p, 8);
        p += __shfl_xor_sync(0xffffffffu, p, 4);
        p += __shfl_xor_sync(0xffffffffu, p, 2);
        p += __shfl_xor_sync(0xffffffffu, p, 1);
        if (lane == c) res = p + sbfc[c];
    }
    if (lane < NCLS) out[warp * NCLS + lane] = res;
}

// ---------------- launch -----------------------------------------------------
extern "C" void kernel_launch(void* const* d_in, const int* in_sizes, int n_in,
                              void* d_out, int out_size) {
    const float* x   = (const float*)d_in[0];
    const int*   ei  = (const int*)d_in[1];   // int32: JAX x64-disabled downcast
    const float* W1  = (const float*)d_in[2];
    const float* b1  = (const float*)d_in[3];
    const float* W2  = (const float*)d_in[4];
    const float* b2  = (const float*)d_in[5];
    const float* Wfc = (const float*)d_in[6];
    const float* bfc = (const float*)d_in[7];
    float* out = (float*)d_out;
    const int* srcp = ei;
    const int* dstp = ei + NE;

    k_zero_deg<<<(NN + 255) / 256, 256>>>();
    k_count<<<(NE + 255) / 256, 256>>>(dstp);
    k_scan1<<<NB, 256>>>();
    k_scan2<<<1, 64>>>();
    k_scan3<<<NB, 256>>>();
    k_fill<<<(NE + 255) / 256, 256>>>(srcp, dstp);

    k_gemm<FEAT, false><<<(NN + 63) / 64, 256>>>(x, W1);     // -> g_xws
    k_agg1<<<(NN + 7) / 8, 256>>>(b1);                        // -> g_h1
    k_gemm<HID, true><<<(NN + 63) / 64, 256>>>(nullptr, W2);  // -> g_xws
    k_agg2<<<(NN + 7) / 8, 256>>>(b2, Wfc, bfc, out);         // -> d_out
}

// round 3
// speedup vs baseline: 1.0161x; 1.0161x over previous
#include <cuda_runtime.h>
#include <cuda_fp16.h>

#define NN 50000
#define NE 800000
#define FEAT 128
#define HID 64
#define NCLS 12
#define SCAN_CHUNK 1024
#define NB ((NN + SCAN_CHUNK - 1) / SCAN_CHUNK)   // 49

// ---------------- scratch (static device globals; no allocation) -------------
__device__ __align__(16) int     g_deg[NN];
__device__ __align__(16) int     g_rowptr[NN + 1];
__device__ __align__(16) int     g_cursor[NN];
__device__ __align__(16) int     g_partial[NB + 8];
__device__ __align__(16) int     g_csr[NE];
__device__ __align__(16) float   g_dinv[NN];
__device__ __align__(16) __half2 g_xws[NN * (HID / 2)];  // (A@W)*dinv, fp16, 128B/row
__device__ __align__(16) float   g_h1[NN * HID];         // layer-1 activations

// ---------------- CSR build --------------------------------------------------
__global__ void k_zero_deg() {
    int i = blockIdx.x * blockDim.x + threadIdx.x;
    if (i < NN) g_deg[i] = 0;
}

__global__ void k_count(const int* __restrict__ dst) {
    int e = blockIdx.x * blockDim.x + threadIdx.x;
    if (e < NE) atomicAdd(&g_deg[dst[e]], 1);
}

// per-chunk (1024) sums
__global__ void k_scan1() {
    __shared__ int wsum[8];
    int t = threadIdx.x, b = blockIdx.x;
    int base = b * SCAN_CHUNK + t * 4;
    int s = 0;
#pragma unroll
    for (int i = 0; i < 4; i++)
        if (base + i < NN) s += g_deg[base + i];
#pragma unroll
    for (int d = 16; d; d >>= 1) s += __shfl_xor_sync(0xffffffffu, s, d);
    if ((t & 31) == 0) wsum[t >> 5] = s;
    __syncthreads();
    if (t == 0) {
        int tot = 0;
#pragma unroll
        for (int i = 0; i < 8; i++) tot += wsum[i];
        g_partial[b] = tot;
    }
}

// exclusive scan of the NB partials (NB=49 <= 64 lanes over 2 warps)
__global__ void k_scan2() {
    __shared__ int w0sum;
    int t = threadIdx.x;               // 64 threads
    int lane = t & 31, wid = t >> 5;
    int v = (t < NB) ? g_partial[t] : 0;
    int sc = v;
#pragma unroll
    for (int d = 1; d < 32; d <<= 1) {
        int n = __shfl_up_sync(0xffffffffu, sc, d);
        if (lane >= d) sc += n;
    }
    if (wid == 0 && lane == 31) w0sum = sc;
    __syncthreads();
    if (wid == 1) sc += w0sum;
    if (t < NB) g_partial[t] = sc - v;  // exclusive
}

// final: rowptr (exclusive), cursor copy, dinv = rsqrt(deg+1)
__global__ void k_scan3() {
    __shared__ int warp_sums[8];
    int t = threadIdx.x, b = blockIdx.x;
    int lane = t & 31, wid = t >> 5;
    int base = b * SCAN_CHUNK + t * 4;
    int v[4];
#pragma unroll
    for (int i = 0; i < 4; i++) v[i] = (base + i < NN) ? g_deg[base + i] : 0;
    int s = v[0] + v[1] + v[2] + v[3];
    int sc = s;
#pragma unroll
    for (int d = 1; d < 32; d <<= 1) {
        int n = __shfl_up_sync(0xffffffffu, sc, d);
        if (lane >= d) sc += n;
    }
    if (lane == 31) warp_sums[wid] = sc;
    __syncthreads();
    if (wid == 0) {
        int ws = (lane < 8) ? warp_sums[lane] : 0;
#pragma unroll
        for (int d = 1; d < 8; d <<= 1) {
            int n = __shfl_up_sync(0xffffffffu, ws, d);
            if (lane >= d) ws += n;
        }
        if (lane < 8) warp_sums[lane] = ws;  // inclusive per-warp totals
    }
    __syncthreads();
    int run = g_partial[b] + (wid ? warp_sums[wid - 1] : 0) + (sc - s);
#pragma unroll
    for (int i = 0; i < 4; i++) {
        int idx = base + i;
        if (idx < NN) {
            g_rowptr[idx] = run;
            g_cursor[idx] = run;
            g_dinv[idx]   = rsqrtf((float)v[i] + 1.0f);
            run += v[i];
        }
    }
    if (b == 0 && t == 0) g_rowptr[NN] = NE;
}

__global__ void k_fill(const int* __restrict__ src,
                       const int* __restrict__ dst) {
    int e = blockIdx.x * blockDim.x + threadIdx.x;
    if (e < NE) {
        int d = dst[e];
        int pos = atomicAdd(&g_cursor[d], 1);
        g_csr[pos] = src[e];
    }
}

// ---------------- GEMM: C = (A @ W) * dinv[row] -> g_xws (fp16) -------------
// A: [NN, K] (external x, or g_h1), W: [K, 64]. Tile: 64 rows/block, 256 thr,
// each thread computes a 4x4 micro-tile.
template <int K, bool A_FROM_H1>
__global__ void k_gemm(const float* __restrict__ Aext, const float* __restrict__ W) {
    const int KB = 64;
    __shared__ float As[64][KB + 4];
    __shared__ float Ws[KB][HID];
    const float* A = A_FROM_H1 ? (const float*)g_h1 : Aext;
    int tid = threadIdx.x;
    int tx = tid & 15;      // 4 output cols: tx*4..+3
    int ty = tid >> 4;      // 4 output rows: ty*4..+3
    int row0 = blockIdx.x * 64;
    float acc[4][4] = {};
    for (int kb = 0; kb < K; kb += KB) {
        for (int i = tid; i < 64 * (KB / 4); i += 256) {
            int r  = i >> 4;
            int c4 = i & 15;
            float4 v = make_float4(0.f, 0.f, 0.f, 0.f);
            int gr = row0 + r;
            if (gr < NN) v = *(const float4*)&A[gr * K + kb + c4 * 4];
            *(float4*)&As[r][c4 * 4] = v;
        }
        for (int i = tid; i < KB * (HID / 4); i += 256) {
            int r  = i >> 4;
            int c4 = i & 15;
            *(float4*)&Ws[r][c4 * 4] = *(const float4*)&W[(kb + r) * HID + c4 * 4];
        }
        __syncthreads();
#pragma unroll 8
        for (int k = 0; k < KB; k++) {
            float a0 = As[ty * 4 + 0][k];
            float a1 = As[ty * 4 + 1][k];
            float a2 = As[ty * 4 + 2][k];
            float a3 = As[ty * 4 + 3][k];
            float4 w = *(const float4*)&Ws[k][tx * 4];
            acc[0][0] += a0 * w.x; acc[0][1] += a0 * w.y; acc[0][2] += a0 * w.z; acc[0][3] += a0 * w.w;
            acc[1][0] += a1 * w.x; acc[1][1] += a1 * w.y; acc[1][2] += a1 * w.z; acc[1][3] += a1 * w.w;
            acc[2][0] += a2 * w.x; acc[2][1] += a2 * w.y; acc[2][2] += a2 * w.z; acc[2][3] += a2 * w.w;
            acc[3][0] += a3 * w.x; acc[3][1] += a3 * w.y; acc[3][2] += a3 * w.z; acc[3][3] += a3 * w.w;
        }
        __syncthreads();
    }
#pragma unroll
    for (int i = 0; i < 4; i++) {
        int r = row0 + ty * 4 + i;
        if (r < NN) {
            float sc = g_dinv[r];
            __half2 h[2];
            h[0] = __floats2half2_rn(acc[i][0] * sc, acc[i][1] * sc);
            h[1] = __floats2half2_rn(acc[i][2] * sc, acc[i][3] * sc);
            // feats tx*4..tx*4+3 -> half2 slots tx*2, tx*2+1 (8B store)
            *(uint2*)&g_xws[r * (HID / 2) + tx * 2] = *(uint2*)h;
        }
    }
}

// ---------------- aggregation: warp per dst node ----------------------------
// acc = sum_{j in N(i)} xws[j] ; out = dinv[i]*(acc + xws[i]) + b
// Row is 128B fp16: lane reads one half2 (feats 2*lane, 2*lane+1).
__device__ __forceinline__ void agg_row(int node, int lane, float& a0, float& a1) {
    int beg = g_rowptr[node];
    int end = g_rowptr[node + 1];
    a0 = 0.f; a1 = 0.f;
    for (int base = beg; base < end; base += 32) {
        int idx = base + lane;
        int s_l = (idx < end) ? g_csr[idx] : 0;
        int iters = end - base;
        if (iters > 32) iters = 32;
#pragma unroll 4
        for (int j = 0; j < iters; j++) {
            int s = __shfl_sync(0xffffffffu, s_l, j);
            float2 v = __half22float2(g_xws[s * (HID / 2) + lane]);
            a0 += v.x;
            a1 += v.y;
        }
    }
}

__global__ void k_agg1(const float* __restrict__ b1) {
    int warp = (blockIdx.x * blockDim.x + threadIdx.x) >> 5;
    int lane = threadIdx.x & 31;
    if (warp >= NN) return;
    float a0, a1;
    agg_row(warp, lane, a0, a1);
    float dd = g_dinv[warp];
    float2 sv = __half22float2(g_xws[warp * (HID / 2) + lane]);
    float r0 = fmaxf(fmaf(dd, a0 + sv.x, b1[2 * lane + 0]), 0.f);
    float r1 = fmaxf(fmaf(dd, a1 + sv.y, b1[2 * lane + 1]), 0.f);
    *(float2*)&g_h1[warp * HID + 2 * lane] = make_float2(r0, r1);
}

// layer-2 aggregation fused with the 64->12 FC + bfc. Writes d_out directly.
__global__ void k_agg2(const float* __restrict__ b2, const float* __restrict__ Wfc,
                       const float* __restrict__ bfc, float* __restrict__ out) {
    __shared__ float sW[HID * NCLS];
    __shared__ float sb2[HID];
    __shared__ float sbfc[NCLS];
    int tid = threadIdx.x;
    for (int i = tid; i < HID * NCLS; i += 256) sW[i] = Wfc[i];
    if (tid < HID)  sb2[tid]  = b2[tid];
    if (tid < NCLS) sbfc[tid] = bfc[tid];
    __syncthreads();

    int warp = (blockIdx.x * blockDim.x + tid) >> 5;
    int lane = tid & 31;
    if (warp >= NN) return;
    float a0, a1;
    agg_row(warp, lane, a0, a1);
    float dd = g_dinv[warp];
    float2 sv = __half22float2(g_xws[warp * (HID / 2) + lane]);
    float t0 = fmaxf(fmaf(dd, a0 + sv.x, sb2[2 * lane + 0]), 0.f);
    float t1 = fmaxf(fmaf(dd, a1 + sv.y, sb2[2 * lane + 1]), 0.f);

    // FC: out[c] = sum_k h2[k] * Wfc[k][c] + bfc[c]
    float res = 0.f;
#pragma unroll
    for (int c = 0; c < NCLS; c++) {
        float p = t0 * sW[(2 * lane + 0) * NCLS + c] + t1 * sW[(2 * lane + 1) * NCLS + c];
        p += __shfl_xor_sync(0xffffffffu, p, 16);
        p += __shfl_xor_sync(0xffffffffu, p, 8);
        p += __shfl_xor_sync(0xffffffffu, p, 4);
        p += __shfl_xor_sync(0xffffffffu, p, 2);
        p += __shfl_xor_sync(0xffffffffu, p, 1);
        if (lane == c) res = p + sbfc[c];
    }
    if (lane < NCLS) out[warp * NCLS + lane] = res;
}

// ---------------- launch -----------------------------------------------------
extern "C" void kernel_launch(void* const* d_in, const int* in_sizes, int n_in,
                              void* d_out, int out_size) {
    const float* x   = (const float*)d_in[0];
    const int*   ei  = (const int*)d_in[1];   // int32 (JAX x64-disabled)
    const float* W1  = (const float*)d_in[2];
    const float* b1  = (const float*)d_in[3];
    const float* W2  = (const float*)d_in[4];
    const float* b2  = (const float*)d_in[5];
    const float* Wfc = (const float*)d_in[6];
    const float* bfc = (const float*)d_in[7];
    float* out = (float*)d_out;
    const int* srcp = ei;
    const int* dstp = ei + NE;

    k_zero_deg<<<(NN + 255) / 256, 256>>>();
    k_count<<<(NE + 255) / 256, 256>>>(dstp);
    k_scan1<<<NB, 256>>>();
    k_scan2<<<1, 64>>>();
    k_scan3<<<NB, 256>>>();
    k_fill<<<(NE + 255) / 256, 256>>>(srcp, dstp);

    k_gemm<FEAT, false><<<(NN + 63) / 64, 256>>>(x, W1);     // -> g_xws (fp16)
    k_agg1<<<(NN + 7) / 8, 256>>>(b1);                        // -> g_h1
    k_gemm<HID, true><<<(NN + 63) / 64, 256>>>(nullptr, W2);  // -> g_xws (fp16)
    k_agg2<<<(NN + 7) / 8, 256>>>(b2, Wfc, bfc, out);         // -> d_out
}